// round 11
// baseline (speedup 1.0000x reference)
#include <cuda_runtime.h>
#include <cuda_fp16.h>
#include <cstdint>

// ============================================================================
// HiPPO-LegT scan via chunked GEMM on mma.sync (HMMA fp16, base sm_103).
//   c_t = A c_{t-1} + f_t B ;  out (512, 2048, 64)
// Chunk T=16:  OUT[c][(j,n)] = sum_k X[c][k] * G[(j,n)][k],  K = 80.
// Single fp16 pass (validated: rel_err 2.87e-4).
// R11: G rows stored PERMUTED (physical pn=8*nt+2q+e <-> logical n=16q+2nt+e)
// so each thread's accumulators are contiguous -> float4 streaming stores.
// Prep collapsed to ONE launch (16 independent CTAs, per-CTA powering).
// ============================================================================

static constexpr int TCH    = 16;
static constexpr int NCHUNK = 32;
static constexpr int NSEQ   = 2048;
static constexpr int NCOLS  = NSEQ * NCHUNK;   // 65536
static constexpr int KREAL  = 80;
static constexpr int SEQLEN = 512;
static constexpr int KPADB  = 176;             // smem row pitch bytes (88 halves)
static constexpr int MT     = 128;             // X columns per CTA

// ---- device scratch (static; no cudaMalloc) ----
__device__ __align__(16) float   g_Apow16[4096];
__device__ __align__(16) float   g_Kvec[16 * 64];
__device__ __align__(16) __half  g_Gh[1024 * KREAL];
__device__ __align__(16) __half  g_Xh[(size_t)NCOLS * KREAL];

// ---- packed f32x2 helpers ----
__device__ __forceinline__ double fma2(double a, double b, double c) {
    double d; asm("fma.rn.f32x2 %0, %1, %2, %3;" : "=d"(d) : "d"(a), "d"(b), "d"(c)); return d;
}
__device__ __forceinline__ double add2(double a, double b) {
    double d; asm("add.rn.f32x2 %0, %1, %2;" : "=d"(d) : "d"(a), "d"(b)); return d;
}
__device__ __forceinline__ double pack2(float lo, float hi) {
    double d; asm("mov.b64 %0, {%1, %2};" : "=d"(d) : "f"(lo), "f"(hi)); return d;
}
__device__ __forceinline__ void unpack2(double d, float& lo, float& hi) {
    asm("mov.b64 {%0, %1}, %2;" : "=f"(lo), "=f"(hi) : "d"(d));
}

// ---- mma / ldmatrix / cp.async ----
__device__ __forceinline__ uint32_t smem_u32(const void* p) {
    uint32_t a;
    asm("{ .reg .u64 t; cvta.to.shared.u64 t, %1; cvt.u32.u64 %0, t; }" : "=r"(a) : "l"(p));
    return a;
}
__device__ __forceinline__ void mma16816(float* d, const uint32_t* a, uint32_t b0, uint32_t b1) {
    asm volatile(
        "mma.sync.aligned.m16n8k16.row.col.f32.f16.f16.f32 "
        "{%0,%1,%2,%3}, {%4,%5,%6,%7}, {%8,%9}, {%0,%1,%2,%3};\n"
        : "+f"(d[0]), "+f"(d[1]), "+f"(d[2]), "+f"(d[3])
        : "r"(a[0]), "r"(a[1]), "r"(a[2]), "r"(a[3]), "r"(b0), "r"(b1));
}
__device__ __forceinline__ void ldsm_x4(uint32_t* r, uint32_t addr) {
    asm volatile("ldmatrix.sync.aligned.m8n8.x4.shared.b16 {%0,%1,%2,%3}, [%4];"
                 : "=r"(r[0]), "=r"(r[1]), "=r"(r[2]), "=r"(r[3]) : "r"(addr));
}
__device__ __forceinline__ void cp_async16(uint32_t smem, const void* g) {
    asm volatile("cp.async.cg.shared.global [%0], [%1], 16;" :: "r"(smem), "l"(g));
}
__device__ __forceinline__ void cp_commit() { asm volatile("cp.async.commit_group;" ::: "memory"); }
__device__ __forceinline__ void cp_wait0()  { asm volatile("cp.async.wait_group 0;"  ::: "memory"); }

// ---- register-blocked 64x64x64 matmul: D = L @ R, 256 threads ----
__device__ __forceinline__ void mm64(const float* __restrict__ L,
                                     const float* __restrict__ R,
                                     float* __restrict__ D, int t) {
    if (t < 256) {
        const int r0 = (t >> 4) * 4;
        const int c4 = (t & 15);
        const float4* L4 = reinterpret_cast<const float4*>(L);
        const float4* R4 = reinterpret_cast<const float4*>(R);
        float4 acc0 = make_float4(0.f, 0.f, 0.f, 0.f);
        float4 acc1 = acc0, acc2 = acc0, acc3 = acc0;
        #pragma unroll
        for (int v = 0; v < 16; v++) {
            const float4 a0 = L4[(r0 + 0) * 16 + v];
            const float4 a1 = L4[(r0 + 1) * 16 + v];
            const float4 a2 = L4[(r0 + 2) * 16 + v];
            const float4 a3 = L4[(r0 + 3) * 16 + v];
            const float4 b0 = R4[(4 * v + 0) * 16 + c4];
            const float4 b1 = R4[(4 * v + 1) * 16 + c4];
            const float4 b2 = R4[(4 * v + 2) * 16 + c4];
            const float4 b3 = R4[(4 * v + 3) * 16 + c4];
            acc0.x = fmaf(a0.x, b0.x, acc0.x); acc0.y = fmaf(a0.x, b0.y, acc0.y);
            acc0.z = fmaf(a0.x, b0.z, acc0.z); acc0.w = fmaf(a0.x, b0.w, acc0.w);
            acc0.x = fmaf(a0.y, b1.x, acc0.x); acc0.y = fmaf(a0.y, b1.y, acc0.y);
            acc0.z = fmaf(a0.y, b1.z, acc0.z); acc0.w = fmaf(a0.y, b1.w, acc0.w);
            acc0.x = fmaf(a0.z, b2.x, acc0.x); acc0.y = fmaf(a0.z, b2.y, acc0.y);
            acc0.z = fmaf(a0.z, b2.z, acc0.z); acc0.w = fmaf(a0.z, b2.w, acc0.w);
            acc0.x = fmaf(a0.w, b3.x, acc0.x); acc0.y = fmaf(a0.w, b3.y, acc0.y);
            acc0.z = fmaf(a0.w, b3.z, acc0.z); acc0.w = fmaf(a0.w, b3.w, acc0.w);

            acc1.x = fmaf(a1.x, b0.x, acc1.x); acc1.y = fmaf(a1.x, b0.y, acc1.y);
            acc1.z = fmaf(a1.x, b0.z, acc1.z); acc1.w = fmaf(a1.x, b0.w, acc1.w);
            acc1.x = fmaf(a1.y, b1.x, acc1.x); acc1.y = fmaf(a1.y, b1.y, acc1.y);
            acc1.z = fmaf(a1.y, b1.z, acc1.z); acc1.w = fmaf(a1.y, b1.w, acc1.w);
            acc1.x = fmaf(a1.z, b2.x, acc1.x); acc1.y = fmaf(a1.z, b2.y, acc1.y);
            acc1.z = fmaf(a1.z, b2.z, acc1.z); acc1.w = fmaf(a1.z, b2.w, acc1.w);
            acc1.x = fmaf(a1.w, b3.x, acc1.x); acc1.y = fmaf(a1.w, b3.y, acc1.y);
            acc1.z = fmaf(a1.w, b3.z, acc1.z); acc1.w = fmaf(a1.w, b3.w, acc1.w);

            acc2.x = fmaf(a2.x, b0.x, acc2.x); acc2.y = fmaf(a2.x, b0.y, acc2.y);
            acc2.z = fmaf(a2.x, b0.z, acc2.z); acc2.w = fmaf(a2.x, b0.w, acc2.w);
            acc2.x = fmaf(a2.y, b1.x, acc2.x); acc2.y = fmaf(a2.y, b1.y, acc2.y);
            acc2.z = fmaf(a2.y, b1.z, acc2.z); acc2.w = fmaf(a2.y, b1.w, acc2.w);
            acc2.x = fmaf(a2.z, b2.x, acc2.x); acc2.y = fmaf(a2.z, b2.y, acc2.y);
            acc2.z = fmaf(a2.z, b2.z, acc2.z); acc2.w = fmaf(a2.z, b2.w, acc2.w);
            acc2.x = fmaf(a2.w, b3.x, acc2.x); acc2.y = fmaf(a2.w, b3.y, acc2.y);
            acc2.z = fmaf(a2.w, b3.z, acc2.z); acc2.w = fmaf(a2.w, b3.w, acc2.w);

            acc3.x = fmaf(a3.x, b0.x, acc3.x); acc3.y = fmaf(a3.x, b0.y, acc3.y);
            acc3.z = fmaf(a3.x, b0.z, acc3.z); acc3.w = fmaf(a3.x, b0.w, acc3.w);
            acc3.x = fmaf(a3.y, b1.x, acc3.x); acc3.y = fmaf(a3.y, b1.y, acc3.y);
            acc3.z = fmaf(a3.y, b1.z, acc3.z); acc3.w = fmaf(a3.y, b1.w, acc3.w);
            acc3.x = fmaf(a3.z, b2.x, acc3.x); acc3.y = fmaf(a3.z, b2.y, acc3.y);
            acc3.z = fmaf(a3.z, b2.z, acc3.z); acc3.w = fmaf(a3.z, b2.w, acc3.w);
            acc3.x = fmaf(a3.w, b3.x, acc3.x); acc3.y = fmaf(a3.w, b3.y, acc3.y);
            acc3.z = fmaf(a3.w, b3.z, acc3.z); acc3.w = fmaf(a3.w, b3.w, acc3.w);
        }
        float4* D4 = reinterpret_cast<float4*>(D);
        D4[(r0 + 0) * 16 + c4] = acc0;
        D4[(r0 + 1) * 16 + c4] = acc1;
        D4[(r0 + 2) * 16 + c4] = acc2;
        D4[(r0 + 3) * 16 + c4] = acc3;
    }
    __syncthreads();
}

// ============================================================================
// Prep: ONE launch, 16 independent CTAs x 256 threads, dynamic smem 104 KB.
// CTA j: K chain (d<=j), squares S2/S4/S8[/S16], product A^(j+1), writes its
// 64 PERMUTED G rows.  CTA 15 publishes A^16 and Kvec for phase1.
// ============================================================================
__global__ __launch_bounds__(256) void prep_kernel(const float* __restrict__ A,
                                                   const float* __restrict__ Bvec) {
    extern __shared__ __align__(16) float dyn[];
    float* buf0 = dyn;              // A
    float* buf1 = dyn + 4096;       // S2
    float* buf2 = dyn + 8192;       // S4
    float* buf3 = dyn + 12288;      // S8
    float* buf4 = dyn + 16384;      // product ping
    float* buf5 = dyn + 20480;      // product pong
    float* sK   = dyn + 24576;      // 16 x 64

    const int t = threadIdx.x;
    const int j = blockIdx.x;
    const int p = j + 1;

    for (int i = t; i < 4096; i += 256) buf0[i] = A[i];
    if (t < 64) sK[t] = Bvec[t];
    __syncthreads();

    // K chain: K_d = A @ K_{d-1}, d = 1..j
    for (int d = 1; d <= j; d++) {
        float s = 0.0f;
        if (t < 64) {
            const float4* ar = reinterpret_cast<const float4*>(&buf0[t * 64]);
            const float4* kr = reinterpret_cast<const float4*>(&sK[(d - 1) * 64]);
            float s0 = 0.f, s1 = 0.f, s2 = 0.f, s3 = 0.f;
            #pragma unroll
            for (int v = 0; v < 16; v++) {
                const float4 a = ar[v], b = kr[v];
                s0 = fmaf(a.x, b.x, s0); s1 = fmaf(a.y, b.y, s1);
                s2 = fmaf(a.z, b.z, s2); s3 = fmaf(a.w, b.w, s3);
            }
            s = (s0 + s1) + (s2 + s3);
        }
        __syncthreads();
        if (t < 64) sK[d * 64 + t] = s;
        __syncthreads();
    }

    // squares as needed
    if (p >= 2) mm64(buf0, buf0, buf1, t);   // S2
    if (p >= 4) mm64(buf1, buf1, buf2, t);   // S4
    if (p >= 8) mm64(buf2, buf2, buf3, t);   // S8

    const float* P;
    if (p == 16) {
        mm64(buf3, buf3, buf4, t);           // S16
        P = buf4;
    } else {
        const float* f[4];
        int nf = 0;
        if (p & 1) f[nf++] = buf0;
        if (p & 2) f[nf++] = buf1;
        if (p & 4) f[nf++] = buf2;
        if (p & 8) f[nf++] = buf3;
        P = f[0];
        float* dst = buf4;
        for (int i2 = 1; i2 < nf; i2++) {
            mm64(P, f[i2], dst, t);
            P = dst;
            dst = (dst == buf4) ? buf5 : buf4;
        }
    }

    // G rows, PERMUTED: physical pn -> logical n = 16*((pn&7)>>1) + 2*(pn>>3) + (pn&1)
    for (int idx = t; idx < 64 * KREAL; idx += 256) {
        const int pn = idx / KREAL, k = idx % KREAL;
        const int n = 16 * ((pn & 7) >> 1) + 2 * (pn >> 3) + (pn & 1);
        float v;
        if (k < 64) v = P[n * 64 + k];
        else {
            const int d = j - (k - 64);
            v = (d < 0) ? 0.0f : sK[d * 64 + n];
        }
        g_Gh[(size_t)(j * 64 + pn) * KREAL + k] = __float2half(v);
    }
    if (j == 15) {
        for (int i = t; i < 4096; i += 256) g_Apow16[i] = P[i];
        for (int i = t; i < 1024; i += 256) g_Kvec[i] = sK[i];
    }
}

// ============================================================================
// Phase 1: boundary scan (fp32, f32x2) + X build (fp16). 2048 x 64.
// ============================================================================
__global__ __launch_bounds__(64) void phase1_kernel(const float* __restrict__ xin) {
    const int seq = blockIdx.x, n = threadIdx.x;
    __shared__ __align__(16) float c_sm[2][64];
    __shared__ __align__(16) float f_sm[2][16];

    double a16[32];
    {
        const double* r = reinterpret_cast<const double*>(&g_Apow16[n * 64]);
        #pragma unroll
        for (int i = 0; i < 32; i++) a16[i] = r[i];
    }
    double wp[8];
    #pragma unroll
    for (int i = 0; i < 8; i++)
        wp[i] = pack2(g_Kvec[(15 - 2 * i) * 64 + n], g_Kvec[(14 - 2 * i) * 64 + n]);

    float cmy = 0.0f;
    c_sm[0][n] = 0.0f;

    for (int k = 0; k < NCHUNK; k++) {
        const int buf = k & 1;
        const size_t col = (size_t)k * NSEQ + seq;
        g_Xh[col * KREAL + n] = __float2half(cmy);
        if (n < 16) {
            const float f = xin[(size_t)seq * SEQLEN + k * TCH + n];
            f_sm[buf][n] = f;
            g_Xh[col * KREAL + 64 + n] = __float2half(f);
        }
        __syncthreads();

        const double2* cp = reinterpret_cast<const double2*>(c_sm[buf]);
        double acc0 = 0.0, acc1 = 0.0, acc2 = 0.0, acc3 = 0.0;
        #pragma unroll
        for (int i = 0; i < 8; i++) {
            const double2 ca = cp[2 * i], cb = cp[2 * i + 1];
            acc0 = fma2(a16[4 * i],     ca.x, acc0);
            acc1 = fma2(a16[4 * i + 1], ca.y, acc1);
            acc2 = fma2(a16[4 * i + 2], cb.x, acc2);
            acc3 = fma2(a16[4 * i + 3], cb.y, acc3);
        }
        const double* fp = reinterpret_cast<const double*>(f_sm[buf]);
        acc0 = fma2(wp[0], fp[0], acc0); acc1 = fma2(wp[1], fp[1], acc1);
        acc2 = fma2(wp[2], fp[2], acc2); acc3 = fma2(wp[3], fp[3], acc3);
        acc0 = fma2(wp[4], fp[4], acc0); acc1 = fma2(wp[5], fp[5], acc1);
        acc2 = fma2(wp[6], fp[6], acc2); acc3 = fma2(wp[7], fp[7], acc3);

        const double s = add2(add2(acc0, acc1), add2(acc2, acc3));
        float x, y;
        unpack2(s, x, y);
        cmy = x + y;
        c_sm[buf ^ 1][n] = cmy;
    }
}

// ============================================================================
// GEMM: grid (512, 8) x 256 thr.  CTA: 128 X-cols x 2 jt, ONE barrier.
// Arena 45056 B: [Xh 22528 | G(j0) 11264 | G(j0+1) 11264].
// Permuted G -> each thread's 16 accs per row are contiguous -> float4 stores.
// ============================================================================
__global__ __launch_bounds__(256) void gemm_kernel(float* __restrict__ out) {
    __shared__ __align__(16) char arena[45056];

    const int tid = threadIdx.x;
    const int w = tid >> 5, l = tid & 31;
    const int mbase = blockIdx.x * MT;        // 512 blocks
    const int j0    = blockIdx.y * 2;         // 8 blocks
    const uint32_t base = smem_u32(arena);

    // ---- prologue: X (128 rows) + G(j0), G(j0+1) ----
    for (int c = tid; c < 1280; c += 256) {
        const int row = c / 10, part = c % 10;
        cp_async16(base + row * KPADB + part * 16,
                   (const char*)(g_Xh + (size_t)(mbase + row) * KREAL) + part * 16);
    }
    for (int c = tid; c < 1280; c += 256) {
        const int g = c / 640, rem = c % 640;
        const int row = rem / 10, part = rem % 10;
        cp_async16(base + 22528 + g * 11264 + row * KPADB + part * 16,
                   (const char*)(g_Gh + (size_t)((j0 + g) * 64 + row) * KREAL) + part * 16);
    }
    cp_commit(); cp_wait0();
    __syncthreads();

    const int jl = w >> 2;                    // 0/1
    const int mq = w & 3;                     // 0..3
    const int jt = j0 + jl;

    const uint32_t aoff = base + (uint32_t)(mq * 32 + (l & 15)) * KPADB + ((l >> 4) * 16);
    const uint32_t gbuf = base + 22528 + jl * 11264;
    const uint32_t boff = gbuf + (uint32_t)((l & 7) + ((l & 16) >> 1)) * KPADB + ((l & 8) << 1);

    float acc[2][8][4];
    #pragma unroll
    for (int mt = 0; mt < 2; mt++)
        #pragma unroll
        for (int nt = 0; nt < 8; nt++)
            #pragma unroll
            for (int q = 0; q < 4; q++) acc[mt][nt][q] = 0.0f;

    #pragma unroll
    for (int ks = 0; ks < 5; ks++) {
        uint32_t bh[4][4];
        #pragma unroll
        for (int p = 0; p < 4; p++)
            ldsm_x4(bh[p], boff + p * (16 * KPADB) + ks * 32);
        #pragma unroll
        for (int mt = 0; mt < 2; mt++) {
            uint32_t a4[4];
            ldsm_x4(a4, aoff + mt * (16 * KPADB) + ks * 32);
            #pragma unroll
            for (int p = 0; p < 4; p++)
                #pragma unroll
                for (int hh = 0; hh < 2; hh++)
                    mma16816(acc[mt][p * 2 + hh], a4, bh[p][2 * hh], bh[p][2 * hh + 1]);
        }
    }

    // ---- epilogue: permuted-G makes thread's 16 values contiguous ----
    const int chunk = mbase >> 11;
    const int seqb  = mbase & 2047;
    const int q     = l & 3;
    float* obase = out + (size_t)(chunk * TCH + jt) * NSEQ * 64 + 16 * q;
    #pragma unroll
    for (int mt = 0; mt < 2; mt++)
        #pragma unroll
        for (int s = 0; s < 2; s++) {
            const int m = mq * 32 + mt * 16 + (l >> 2) + s * 8;
            float* ob = obase + (size_t)(seqb + m) * 64;
            #pragma unroll
            for (int j4 = 0; j4 < 4; j4++) {
                float4 v = make_float4(acc[mt][2 * j4][2 * s],
                                       acc[mt][2 * j4][2 * s + 1],
                                       acc[mt][2 * j4 + 1][2 * s],
                                       acc[mt][2 * j4 + 1][2 * s + 1]);
                __stcs(reinterpret_cast<float4*>(ob + 4 * j4), v);
            }
        }
}

// ============================================================================
extern "C" void kernel_launch(void* const* d_in, const int* in_sizes, int n_in,
                              void* d_out, int out_size) {
    const float* xin  = (const float*)d_in[0];  // (16,128,512)
    const float* Amat = (const float*)d_in[1];  // (64,64)
    const float* Bvec = (const float*)d_in[2];  // (64,)
    float* out = (float*)d_out;                 // (512,16,128,64)

    static bool attr_done = false;
    if (!attr_done) {
        cudaFuncSetAttribute(prep_kernel,
                             cudaFuncAttributeMaxDynamicSharedMemorySize, 102400 + 4096);
        attr_done = true;
    }

    prep_kernel<<<16, 256, 102400 + 4096>>>(Amat, Bvec);
    phase1_kernel<<<NSEQ, 64>>>(xin);
    dim3 ggrid(NCOLS / MT, 8);                  // (512, 8)
    gemm_kernel<<<ggrid, 256>>>(out);
}